// round 1
// baseline (speedup 1.0000x reference)
#include <cuda_runtime.h>
#include <math.h>

// Problem constants
#define B_ 4
#define T_ 4096
#define F_ 131          // 1 mean + 128 z + 1 v + 1 noise
#define D_ 128
#define TILE 128
#define NT (T_/TILE)                 // 32 tiles per dim
#define NPAIR (NT*(NT+1)/2)          // 528 triangular tile pairs
#define SA_STRIDE 132                // padded k-major tile stride (floats)
#define JITTER_ 1e-6f

// scratch: per-row squared norm of z (unscaled)
__device__ float g_sq[B_ * T_];

// ---------------------------------------------------------------------------
// Prologue: mean copy + per-row sum(z^2). One warp per row, coalesced loads.
// ---------------------------------------------------------------------------
__global__ void __launch_bounds__(256) pre_kernel(const float* __restrict__ in,
                                                  float* __restrict__ mean_out) {
    int warp = (blockIdx.x * blockDim.x + threadIdx.x) >> 5;
    int lane = threadIdx.x & 31;
    if (warp >= B_ * T_) return;
    const float* row = in + (size_t)warp * F_;
    float s = 0.f;
#pragma unroll
    for (int k = 0; k < 4; k++) {
        float z = row[1 + lane + 32 * k];
        s += z * z;
    }
#pragma unroll
    for (int off = 16; off; off >>= 1) s += __shfl_xor_sync(0xffffffffu, s, off);
    if (lane == 0) {
        g_sq[warp] = s;
        mean_out[warp] = row[0];
    }
}

__device__ __forceinline__ float softplus_f(float x) {
    // numerically stable log(1+exp(x))
    return fmaxf(x, 0.f) + log1pf(__expf(-fabsf(x)));
}

// ---------------------------------------------------------------------------
// Main: per (batch, triangular tile pair) compute 128x128 RBF tile.
// 256 threads, 8x8 register blocking. SMEM tiles stored k-major (transposed)
// with pad 132 so frag loads are float4 and tile stores are <=4-way conflicted.
// Off-diagonal tiles: mirror written via SMEM transpose (y_cov == f_cov there).
// ---------------------------------------------------------------------------
extern __shared__ float smem[];

__global__ void __launch_bounds__(256) cov_kernel(const float* __restrict__ in,
                                                  float* __restrict__ fcov,
                                                  float* __restrict__ ycov) {
    const int b = blockIdx.y;
    int u = blockIdx.x;
    int ti = 0;
    while (u >= NT - ti) { u -= NT - ti; ti++; }
    const int tj = ti + u;
    const int i0 = ti * TILE, j0 = tj * TILE;

    float* sa = smem;                         // [128][132] k-major, rows of i-tile
    float* sb = smem + TILE * SA_STRIDE;      // [128][132] k-major, rows of j-tile

    const int tid  = threadIdx.x;
    const int warp = tid >> 5;
    const int lane = tid & 31;

    const float* base = in + (size_t)b * T_ * F_;

    // Load both tiles, transposed into k-major SMEM.
    // warp handles row r, lane handles 4 feature columns -> coalesced LDG.
#pragma unroll 1
    for (int it = 0; it < 16; it++) {
        int r = it * 8 + warp;
        const float* rowi = base + (size_t)(i0 + r) * F_ + 1;
        const float* rowj = base + (size_t)(j0 + r) * F_ + 1;
#pragma unroll
        for (int k = 0; k < 4; k++) {
            int c = lane + 32 * k;
            sa[c * SA_STRIDE + r] = __ldg(rowi + c);
            sb[c * SA_STRIDE + r] = __ldg(rowj + c);
        }
    }
    __syncthreads();

    const int tm = tid >> 4;   // 0..15 : i-subtile
    const int tn = tid & 15;   // 0..15 : j-subtile

    float acc[8][8];
#pragma unroll
    for (int a = 0; a < 8; a++)
#pragma unroll
        for (int c = 0; c < 8; c++) acc[a][c] = 0.f;

    const float* pa = sa + tm * 8;
    const float* pb = sb + tn * 8;

#pragma unroll 8
    for (int k = 0; k < D_; k++) {
        float4 a0 = *(const float4*)(pa + k * SA_STRIDE);
        float4 a1 = *(const float4*)(pa + k * SA_STRIDE + 4);
        float4 b0 = *(const float4*)(pb + k * SA_STRIDE);
        float4 b1 = *(const float4*)(pb + k * SA_STRIDE + 4);
        float av[8] = {a0.x, a0.y, a0.z, a0.w, a1.x, a1.y, a1.z, a1.w};
        float bv[8] = {b0.x, b0.y, b0.z, b0.w, b1.x, b1.y, b1.z, b1.w};
#pragma unroll
        for (int a = 0; a < 8; a++)
#pragma unroll
            for (int c = 0; c < 8; c++) acc[a][c] = fmaf(av[a], bv[c], acc[a][c]);
    }

    // Epilogue: quad = (gram - 0.5*(sq_i+sq_j)) / 128 ; f = exp(quad)*v_i*v_j
    float sqi[8], vi[8], sqj[8], vj[8];
#pragma unroll
    for (int a = 0; a < 8; a++) {
        int gi = i0 + tm * 8 + a;
        int gj = j0 + tn * 8 + a;
        sqi[a] = g_sq[b * T_ + gi];
        sqj[a] = g_sq[b * T_ + gj];
        vi[a] = __ldg(base + (size_t)gi * F_ + 1 + D_);
        vj[a] = __ldg(base + (size_t)gj * F_ + 1 + D_);
    }
    const float sc = 1.0f / (float)D_;
#pragma unroll
    for (int a = 0; a < 8; a++) {
#pragma unroll
        for (int c = 0; c < 8; c++) {
            float q = (acc[a][c] - 0.5f * (sqi[a] + sqj[c])) * sc;
            acc[a][c] = __expf(q) * vi[a] * vj[c];
        }
    }

    const size_t matBase = (size_t)b * T_ * T_;
    const bool diag = (ti == tj);

    // Direct (i,j) tile stores: coalesced float4 to both matrices.
#pragma unroll
    for (int a = 0; a < 8; a++) {
        int gi = i0 + tm * 8 + a;
        size_t rowOff = matBase + (size_t)gi * T_ + j0 + tn * 8;
        float fv[8], yv[8];
#pragma unroll
        for (int c = 0; c < 8; c++) { fv[c] = acc[a][c]; yv[c] = acc[a][c]; }
        if (diag && tm == tn) {
            float nz = softplus_f(__ldg(base + (size_t)gi * F_ + (F_ - 1)));
            fv[a] += JITTER_;
            yv[a] += JITTER_ + nz;
        }
        *(float4*)(fcov + rowOff)     = make_float4(fv[0], fv[1], fv[2], fv[3]);
        *(float4*)(fcov + rowOff + 4) = make_float4(fv[4], fv[5], fv[6], fv[7]);
        *(float4*)(ycov + rowOff)     = make_float4(yv[0], yv[1], yv[2], yv[3]);
        *(float4*)(ycov + rowOff + 4) = make_float4(yv[4], yv[5], yv[6], yv[7]);
    }

    // Mirror tile (j,i) for off-diagonal pairs. y_cov == f_cov off-diagonal,
    // so one transpose serves both. Transpose through SMEM (reuse sa region).
    if (!diag) {
        __syncthreads();                 // everyone done reading sa
        float* s = sa;                   // [128][129] transposed buffer: s[n][m]
#pragma unroll
        for (int a = 0; a < 8; a++)
#pragma unroll
            for (int c = 0; c < 8; c++)
                s[(tn * 8 + c) * 129 + tm * 8 + a] = acc[a][c];
        __syncthreads();
#pragma unroll
        for (int a = 0; a < 8; a++) {
            int gj = j0 + tm * 8 + a;    // mirror output row
            size_t rowOff = matBase + (size_t)gj * T_ + i0 + tn * 8;
            float fv[8];
#pragma unroll
            for (int c = 0; c < 8; c++) fv[c] = s[(tm * 8 + a) * 129 + tn * 8 + c];
            float4 v0 = make_float4(fv[0], fv[1], fv[2], fv[3]);
            float4 v1 = make_float4(fv[4], fv[5], fv[6], fv[7]);
            *(float4*)(fcov + rowOff)     = v0;
            *(float4*)(fcov + rowOff + 4) = v1;
            *(float4*)(ycov + rowOff)     = v0;
            *(float4*)(ycov + rowOff + 4) = v1;
        }
    }
}

// ---------------------------------------------------------------------------
extern "C" void kernel_launch(void* const* d_in, const int* in_sizes, int n_in,
                              void* d_out, int out_size) {
    const float* in = (const float*)d_in[0];
    float* out  = (float*)d_out;
    float* mean = out;
    float* fcov = out + (size_t)B_ * T_;
    float* ycov = fcov + (size_t)B_ * T_ * T_;

    // prologue: 1 warp per row, B*T rows
    int warps = B_ * T_;
    pre_kernel<<<(warps * 32 + 255) / 256, 256>>>(in, mean);

    const size_t SMEM = 2ull * TILE * SA_STRIDE * sizeof(float);  // ~135 KB
    cudaFuncSetAttribute(cov_kernel, cudaFuncAttributeMaxDynamicSharedMemorySize,
                         (int)SMEM);
    dim3 grid(NPAIR, B_);
    cov_kernel<<<grid, 256, SMEM>>>(in, fcov, ycov);
}

// round 3
// speedup vs baseline: 2.7165x; 2.7165x over previous
#include <cuda_runtime.h>
#include <cuda_fp16.h>
#include <math.h>
#include <stdint.h>

// ---------------- problem constants ----------------
#define B_ 4
#define T_ 4096
#define F_ 131           // 1 mean + 128 z + 1 v + 1 noise
#define D_ 128
#define TILE 128
#define NT 32            // T_/TILE
#define NPAIR 528        // NT*(NT+1)/2
#define JITTER_ 1e-6f

// per-row precomputed: w = exp(-sq/256)*v ; nsp = softplus(noise)
__device__ float g_w[B_ * T_];
__device__ float g_nsp[B_ * T_];

// ---------------- SMEM layout ----------------
// bf16 tiles: 128 rows x 136 halfs (272 B row stride, 17x16B -> ldmatrix conflict-free)
#define TROW 136
#define TILE_BYTES (128 * TROW * 2)      // 34816
#define AHI_OFF 0
#define ALO_OFF TILE_BYTES
#define BHI_OFF (2 * TILE_BYTES)
#define SMEM_BYTES (3 * TILE_BYTES)      // 104448
// epilogue stage (reuses tile region): 128 x 129 floats = 66048 B
#define SSTRIDE 129

__device__ __forceinline__ uint32_t smem_u32(const void* p) {
    uint32_t a;
    asm("{ .reg .u64 t; cvta.to.shared.u64 t, %1; cvt.u32.u64 %0, t; }"
        : "=r"(a) : "l"(p));
    return a;
}

#define LDMX4(r0, r1, r2, r3, addr)                                        \
    asm volatile("ldmatrix.sync.aligned.m8n8.x4.shared.b16 {%0,%1,%2,%3}, [%4];" \
                 : "=r"(r0), "=r"(r1), "=r"(r2), "=r"(r3) : "r"(addr))

#define MMA16816(c, a0, a1, a2, a3, b0, b1)                                \
    asm volatile(                                                          \
        "mma.sync.aligned.m16n8k16.row.col.f32.f16.f16.f32 "               \
        "{%0,%1,%2,%3}, {%4,%5,%6,%7}, {%8,%9}, {%0,%1,%2,%3};"            \
        : "+f"((c)[0]), "+f"((c)[1]), "+f"((c)[2]), "+f"((c)[3])           \
        : "r"(a0), "r"(a1), "r"(a2), "r"(a3), "r"(b0), "r"(b1))

// fp16 hi/lo split, packed pair
__device__ __forceinline__ void fsplit2(float x0, float x1, uint32_t& hi,
                                        uint32_t& lo) {
    __half h0 = __float2half_rn(x0);
    __half h1 = __float2half_rn(x1);
    __half l0 = __float2half_rn(x0 - __half2float(h0));
    __half l1 = __float2half_rn(x1 - __half2float(h1));
    hi = (uint32_t)__half_as_ushort(h0) | ((uint32_t)__half_as_ushort(h1) << 16);
    lo = (uint32_t)__half_as_ushort(l0) | ((uint32_t)__half_as_ushort(l1) << 16);
}

// ---------------- prologue ----------------
__global__ void __launch_bounds__(256) pre_kernel(const float* __restrict__ in,
                                                  float* __restrict__ mean_out) {
    int warp = (blockIdx.x * blockDim.x + threadIdx.x) >> 5;
    int lane = threadIdx.x & 31;
    if (warp >= B_ * T_) return;
    const float* row = in + (size_t)warp * F_;
    float s = 0.f;
#pragma unroll
    for (int k = 0; k < 4; k++) {
        float z = row[1 + lane + 32 * k];
        s += z * z;
    }
#pragma unroll
    for (int off = 16; off; off >>= 1) s += __shfl_xor_sync(0xffffffffu, s, off);
    if (lane == 0) {
        float v = row[1 + D_];
        float noise = row[F_ - 1];
        g_w[warp] = exp2f(-s * 0.0056355275034725f) * v;  // exp(-s/256)*v
        g_nsp[warp] = fmaxf(noise, 0.f) + log1pf(__expf(-fabsf(noise)));
        mean_out[warp] = row[0];
    }
}

// ---------------- main kernel ----------------
extern __shared__ char smem[];

__global__ void __launch_bounds__(256, 2) cov_kernel(const float* __restrict__ in,
                                                     float* __restrict__ fcov,
                                                     float* __restrict__ ycov) {
    const int b = blockIdx.y;
    int u = blockIdx.x;
    int ti = 0;
    while (u >= NT - ti) { u -= NT - ti; ti++; }
    const int tj = ti + u;
    const int i0 = ti * TILE, j0 = tj * TILE;
    const bool diag = (ti == tj);

    const int tid = threadIdx.x;
    const int wid = tid >> 5;
    const int lane = tid & 31;
    const uint32_t sb = smem_u32(smem);

    // ---- load + fp16 split into SMEM ----
    const float* base = in + (size_t)b * T_ * F_;
#pragma unroll 4
    for (int it = 0; it < 32; it++) {
        int p = it * 256 + tid;          // 0..8191 (128 rows x 64 col-pairs)
        int r = p >> 6;
        int c2 = (p & 63) * 2;
        uint32_t soff = (uint32_t)(r * (TROW * 2) + c2 * 2);
        {
            const float* rp = base + (size_t)(i0 + r) * F_ + 1 + c2;
            float x0 = __ldg(rp), x1 = __ldg(rp + 1);
            uint32_t hi, lo;
            fsplit2(x0, x1, hi, lo);
            *(uint32_t*)(smem + AHI_OFF + soff) = hi;
            *(uint32_t*)(smem + ALO_OFF + soff) = lo;
        }
        {
            const float* rp = base + (size_t)(j0 + r) * F_ + 1 + c2;
            float x0 = __ldg(rp), x1 = __ldg(rp + 1);
            __half h0 = __float2half_rn(x0);
            __half h1 = __float2half_rn(x1);
            *(uint32_t*)(smem + BHI_OFF + soff) =
                (uint32_t)__half_as_ushort(h0) |
                ((uint32_t)__half_as_ushort(h1) << 16);
        }
    }
    __syncthreads();

    // ---- MMA: D = (Ahi + Alo) . Bhi^T ----
    const int m0 = (wid & 3) * 32;
    const int n0 = (wid >> 2) * 64;

    float acc[2][8][4];
#pragma unroll
    for (int a = 0; a < 2; a++)
#pragma unroll
        for (int n = 0; n < 8; n++)
#pragma unroll
            for (int q = 0; q < 4; q++) acc[a][n][q] = 0.f;

    // ldmatrix base addresses (byte offsets within SMEM)
    const uint32_t aRowByte = (uint32_t)((m0 + (lane & 15)) * (TROW * 2) +
                                         ((lane >> 4) * 8) * 2);
    const uint32_t bRowByte =
        (uint32_t)((n0 + (lane & 7) + ((lane >> 4) << 3)) * (TROW * 2) +
                   (((lane >> 3) & 1) * 8) * 2);

#pragma unroll 1
    for (int ks = 0; ks < 16; ks++) {
        const uint32_t aTile = (ks < 8) ? AHI_OFF : ALO_OFF;
        const uint32_t koffB = (uint32_t)((ks & 7) * 16 * 2);
        uint32_t ra[2][4];
#pragma unroll
        for (int a = 0; a < 2; a++) {
            uint32_t addr = sb + aTile + aRowByte + a * 16 * (TROW * 2) + koffB;
            LDMX4(ra[a][0], ra[a][1], ra[a][2], ra[a][3], addr);
        }
#pragma unroll
        for (int nt = 0; nt < 4; nt++) {
            uint32_t rb[4];
            uint32_t addr = sb + BHI_OFF + bRowByte + nt * 16 * (TROW * 2) + koffB;
            LDMX4(rb[0], rb[1], rb[2], rb[3], addr);
#pragma unroll
            for (int a = 0; a < 2; a++) {
                MMA16816(acc[a][2 * nt], ra[a][0], ra[a][1], ra[a][2], ra[a][3],
                         rb[0], rb[1]);
                MMA16816(acc[a][2 * nt + 1], ra[a][0], ra[a][1], ra[a][2],
                         ra[a][3], rb[2], rb[3]);
            }
        }
    }
    __syncthreads();   // all warps done reading tiles; reuse SMEM as stage

    // ---- epilogue: f = exp2(g*SC) * w_i * w_j, staged to SMEM ----
    const int bT = b * T_;
    const float SC = 0.011271055006945f;  // log2(e)/128
    float* stage = (float*)smem;

    float wi[2][2], wj[8][2];
#pragma unroll
    for (int a = 0; a < 2; a++)
#pragma unroll
        for (int h = 0; h < 2; h++)
            wi[a][h] = __ldg(g_w + bT + i0 + m0 + a * 16 + (lane >> 2) + h * 8);
#pragma unroll
    for (int nt8 = 0; nt8 < 8; nt8++)
#pragma unroll
        for (int e = 0; e < 2; e++)
            wj[nt8][e] = __ldg(g_w + bT + j0 + n0 + nt8 * 8 + 2 * (lane & 3) + e);

#pragma unroll
    for (int a = 0; a < 2; a++) {
#pragma unroll
        for (int n = 0; n < 8; n++) {
#pragma unroll
            for (int q = 0; q < 4; q++) {
                int r = m0 + a * 16 + (lane >> 2) + (q >> 1) * 8;
                int c = n0 + n * 8 + 2 * (lane & 3) + (q & 1);
                float f = exp2f(acc[a][n][q] * SC) * wi[a][q >> 1] * wj[n][q & 1];
                stage[r * SSTRIDE + c] = f;
            }
        }
    }
    __syncthreads();

    // ---- store phase: conflict-free scalar LDS, coalesced scalar STG ----
    const size_t matBase = (size_t)b * T_ * T_;
#pragma unroll 1
    for (int it = 0; it < 16; it++) {
        int r = it * 8 + wid;
        // direct tile: out row i0+r, cols j0 + lane + 32k
        {
            float nsp = diag ? __ldg(g_nsp + bT + i0 + r) : 0.f;
            size_t rowOff = matBase + (size_t)(i0 + r) * T_ + j0 + lane;
#pragma unroll
            for (int k = 0; k < 4; k++) {
                int c = lane + 32 * k;
                float f = stage[r * SSTRIDE + c];
                float y = f;
                if (diag && c == r) {
                    f += JITTER_;
                    y += JITTER_ + nsp;
                }
                fcov[rowOff + 32 * k] = f;
                ycov[rowOff + 32 * k] = y;
            }
        }
        // mirror tile (off-diagonal only): out row j0+r, cols i0 + lane + 32k
        if (!diag) {
            size_t rowOff = matBase + (size_t)(j0 + r) * T_ + i0 + lane;
#pragma unroll
            for (int k = 0; k < 4; k++) {
                float f = stage[(lane + 32 * k) * SSTRIDE + r];
                fcov[rowOff + 32 * k] = f;
                ycov[rowOff + 32 * k] = f;
            }
        }
    }
}

// ---------------- launch ----------------
extern "C" void kernel_launch(void* const* d_in, const int* in_sizes, int n_in,
                              void* d_out, int out_size) {
    const float* in = (const float*)d_in[0];
    float* out = (float*)d_out;
    float* mean = out;
    float* fcov = out + (size_t)B_ * T_;
    float* ycov = fcov + (size_t)B_ * T_ * T_;

    pre_kernel<<<(B_ * T_ * 32 + 255) / 256, 256>>>(in, mean);

    static int configured = 0;
    if (!configured) {
        cudaFuncSetAttribute(cov_kernel, cudaFuncAttributeMaxDynamicSharedMemorySize,
                             SMEM_BYTES);
        configured = 1;
    }
    dim3 grid(NPAIR, B_);
    cov_kernel<<<grid, 256, SMEM_BYTES>>>(in, fcov, ycov);
}

// round 4
// speedup vs baseline: 3.2242x; 1.1869x over previous
#include <cuda_runtime.h>
#include <cuda_fp16.h>
#include <math.h>
#include <stdint.h>

// ---------------- problem constants ----------------
#define B_ 4
#define T_ 4096
#define F_ 131           // 1 mean + 128 z + 1 v + 1 noise
#define D_ 128
#define TILE 128
#define NT 32            // T_/TILE
#define NPAIR 528        // NT*(NT+1)/2
#define JITTER_ 1e-6f

// per-row precomputed: w = exp(-sq/256)*v ; nsp = softplus(noise)
__device__ float g_w[B_ * T_];
__device__ float g_nsp[B_ * T_];

// ---------------- SMEM layout ----------------
// fp16 tiles: 128 rows x 136 halfs (272 B row stride)
#define TROW 136
#define TILE_BYTES (128 * TROW * 2)      // 34816
#define A_OFF 0
#define B_OFF TILE_BYTES
#define SMEM_BYTES (2 * TILE_BYTES)      // 69632
// epilogue stage (reuses tile region): 128 x 129 floats = 66048 B
#define SSTRIDE 129

__device__ __forceinline__ uint32_t smem_u32(const void* p) {
    uint32_t a;
    asm("{ .reg .u64 t; cvta.to.shared.u64 t, %1; cvt.u32.u64 %0, t; }"
        : "=r"(a) : "l"(p));
    return a;
}

#define LDMX4(r0, r1, r2, r3, addr)                                        \
    asm volatile("ldmatrix.sync.aligned.m8n8.x4.shared.b16 {%0,%1,%2,%3}, [%4];" \
                 : "=r"(r0), "=r"(r1), "=r"(r2), "=r"(r3) : "r"(addr))

#define MMA16816(c, a0, a1, a2, a3, b0, b1)                                \
    asm volatile(                                                          \
        "mma.sync.aligned.m16n8k16.row.col.f32.f16.f16.f32 "               \
        "{%0,%1,%2,%3}, {%4,%5,%6,%7}, {%8,%9}, {%0,%1,%2,%3};"            \
        : "+f"((c)[0]), "+f"((c)[1]), "+f"((c)[2]), "+f"((c)[3])           \
        : "r"(a0), "r"(a1), "r"(a2), "r"(a3), "r"(b0), "r"(b1))

__device__ __forceinline__ void stg_cs(float* p, float v) {
    asm volatile("st.global.cs.f32 [%0], %1;" :: "l"(p), "f"(v) : "memory");
}

__device__ __forceinline__ uint32_t pack_h2(float x0, float x1) {
    __half h0 = __float2half_rn(x0);
    __half h1 = __float2half_rn(x1);
    return (uint32_t)__half_as_ushort(h0) | ((uint32_t)__half_as_ushort(h1) << 16);
}

// ---------------- prologue ----------------
__global__ void __launch_bounds__(256) pre_kernel(const float* __restrict__ in,
                                                  float* __restrict__ mean_out) {
    int warp = (blockIdx.x * blockDim.x + threadIdx.x) >> 5;
    int lane = threadIdx.x & 31;
    if (warp >= B_ * T_) return;
    const float* row = in + (size_t)warp * F_;
    float s = 0.f;
#pragma unroll
    for (int k = 0; k < 4; k++) {
        float z = row[1 + lane + 32 * k];
        s += z * z;
    }
#pragma unroll
    for (int off = 16; off; off >>= 1) s += __shfl_xor_sync(0xffffffffu, s, off);
    if (lane == 0) {
        float v = row[1 + D_];
        float noise = row[F_ - 1];
        g_w[warp] = exp2f(-s * 0.0056355275034725f) * v;  // exp(-s/256)*v
        g_nsp[warp] = fmaxf(noise, 0.f) + log1pf(__expf(-fabsf(noise)));
        mean_out[warp] = row[0];
    }
}

// ---------------- main kernel ----------------
extern __shared__ char smem[];

__global__ void __launch_bounds__(256, 2) cov_kernel(const float* __restrict__ in,
                                                     float* __restrict__ fcov,
                                                     float* __restrict__ ycov) {
    const int b = blockIdx.y;
    int u = blockIdx.x;
    int ti = 0;
    while (u >= NT - ti) { u -= NT - ti; ti++; }
    const int tj = ti + u;
    const int i0 = ti * TILE, j0 = tj * TILE;
    const bool diag = (ti == tj);

    const int tid = threadIdx.x;
    const int wid = tid >> 5;
    const int lane = tid & 31;
    const uint32_t sb = smem_u32(smem);

    // ---- load + fp16 convert into SMEM ----
    const float* base = in + (size_t)b * T_ * F_;
#pragma unroll 4
    for (int it = 0; it < 32; it++) {
        int p = it * 256 + tid;          // 0..8191 (128 rows x 64 col-pairs)
        int r = p >> 6;
        int c2 = (p & 63) * 2;
        uint32_t soff = (uint32_t)(r * (TROW * 2) + c2 * 2);
        {
            const float* rp = base + (size_t)(i0 + r) * F_ + 1 + c2;
            *(uint32_t*)(smem + A_OFF + soff) = pack_h2(__ldg(rp), __ldg(rp + 1));
        }
        {
            const float* rp = base + (size_t)(j0 + r) * F_ + 1 + c2;
            *(uint32_t*)(smem + B_OFF + soff) = pack_h2(__ldg(rp), __ldg(rp + 1));
        }
    }
    __syncthreads();

    // ---- MMA: D = A . B^T (fp16 x fp16 -> fp32) ----
    const int m0 = (wid & 3) * 32;
    const int n0 = (wid >> 2) * 64;

    float acc[2][8][4];
#pragma unroll
    for (int a = 0; a < 2; a++)
#pragma unroll
        for (int n = 0; n < 8; n++)
#pragma unroll
            for (int q = 0; q < 4; q++) acc[a][n][q] = 0.f;

    const uint32_t aRowByte = (uint32_t)((m0 + (lane & 15)) * (TROW * 2) +
                                         ((lane >> 4) * 8) * 2);
    const uint32_t bRowByte =
        (uint32_t)((n0 + (lane & 7) + ((lane >> 4) << 3)) * (TROW * 2) +
                   (((lane >> 3) & 1) * 8) * 2);

#pragma unroll 1
    for (int ks = 0; ks < 8; ks++) {
        const uint32_t koff = (uint32_t)(ks * 16 * 2);
        uint32_t ra[2][4];
#pragma unroll
        for (int a = 0; a < 2; a++) {
            uint32_t addr = sb + A_OFF + aRowByte + a * 16 * (TROW * 2) + koff;
            LDMX4(ra[a][0], ra[a][1], ra[a][2], ra[a][3], addr);
        }
#pragma unroll
        for (int nt = 0; nt < 4; nt++) {
            uint32_t rb[4];
            uint32_t addr = sb + B_OFF + bRowByte + nt * 16 * (TROW * 2) + koff;
            LDMX4(rb[0], rb[1], rb[2], rb[3], addr);
#pragma unroll
            for (int a = 0; a < 2; a++) {
                MMA16816(acc[a][2 * nt], ra[a][0], ra[a][1], ra[a][2], ra[a][3],
                         rb[0], rb[1]);
                MMA16816(acc[a][2 * nt + 1], ra[a][0], ra[a][1], ra[a][2],
                         ra[a][3], rb[2], rb[3]);
            }
        }
    }
    __syncthreads();   // all warps done reading tiles; reuse SMEM as stage

    // ---- epilogue: f = exp2(g*SC) * w_i * w_j, staged to SMEM ----
    const int bT = b * T_;
    const float SC = 0.011271055006945f;  // log2(e)/128
    float* stage = (float*)smem;

    float wi[2][2], wj[8][2];
#pragma unroll
    for (int a = 0; a < 2; a++)
#pragma unroll
        for (int h = 0; h < 2; h++)
            wi[a][h] = __ldg(g_w + bT + i0 + m0 + a * 16 + (lane >> 2) + h * 8);
#pragma unroll
    for (int nt8 = 0; nt8 < 8; nt8++)
#pragma unroll
        for (int e = 0; e < 2; e++)
            wj[nt8][e] = __ldg(g_w + bT + j0 + n0 + nt8 * 8 + 2 * (lane & 3) + e);

#pragma unroll
    for (int a = 0; a < 2; a++) {
#pragma unroll
        for (int n = 0; n < 8; n++) {
#pragma unroll
            for (int q = 0; q < 4; q++) {
                int r = m0 + a * 16 + (lane >> 2) + (q >> 1) * 8;
                int c = n0 + n * 8 + 2 * (lane & 3) + (q & 1);
                float f = exp2f(acc[a][n][q] * SC) * wi[a][q >> 1] * wj[n][q & 1];
                stage[r * SSTRIDE + c] = f;
            }
        }
    }
    __syncthreads();

    // ---- store phase: conflict-free scalar LDS, coalesced streaming STG ----
    const size_t matBase = (size_t)b * T_ * T_;
#pragma unroll 1
    for (int it = 0; it < 16; it++) {
        int r = it * 8 + wid;
        // direct tile: out row i0+r, cols j0 + lane + 32k
        {
            float nsp = diag ? __ldg(g_nsp + bT + i0 + r) : 0.f;
            size_t rowOff = matBase + (size_t)(i0 + r) * T_ + j0 + lane;
#pragma unroll
            for (int k = 0; k < 4; k++) {
                int c = lane + 32 * k;
                float f = stage[r * SSTRIDE + c];
                float y = f;
                if (diag && c == r) {
                    f += JITTER_;
                    y += JITTER_ + nsp;
                }
                stg_cs(fcov + rowOff + 32 * k, f);
                stg_cs(ycov + rowOff + 32 * k, y);
            }
        }
        // mirror tile (off-diagonal only): out row j0+r, cols i0 + lane + 32k
        if (!diag) {
            size_t rowOff = matBase + (size_t)(j0 + r) * T_ + i0 + lane;
#pragma unroll
            for (int k = 0; k < 4; k++) {
                float f = stage[(lane + 32 * k) * SSTRIDE + r];
                stg_cs(fcov + rowOff + 32 * k, f);
                stg_cs(ycov + rowOff + 32 * k, f);
            }
        }
    }
}

// ---------------- launch ----------------
extern "C" void kernel_launch(void* const* d_in, const int* in_sizes, int n_in,
                              void* d_out, int out_size) {
    const float* in = (const float*)d_in[0];
    float* out = (float*)d_out;
    float* mean = out;
    float* fcov = out + (size_t)B_ * T_;
    float* ycov = fcov + (size_t)B_ * T_ * T_;

    pre_kernel<<<(B_ * T_ * 32 + 255) / 256, 256>>>(in, mean);

    static int configured = 0;
    if (!configured) {
        cudaFuncSetAttribute(cov_kernel, cudaFuncAttributeMaxDynamicSharedMemorySize,
                             SMEM_BYTES);
        configured = 1;
    }
    dim3 grid(NPAIR, B_);
    cov_kernel<<<grid, 256, SMEM_BYTES>>>(in, fcov, ycov);
}